// round 15
// baseline (speedup 1.0000x reference)
#include <cuda_runtime.h>
#include <cuda_fp16.h>
#include <cuda.h>
#include <cstdint>
#include <math.h>

// ---------------- problem constants ----------------
#define BB   1024
#define UU   2048
#define GK   4096            // GEMM K = 2U
#define GN   8192            // GEMM N = 4U

// ---------------- arch gate ----------------
#if defined(__CUDA_ARCH__) && (defined(__CUDA_ARCH_FEAT_SM103_ALL) || \
                               defined(__CUDA_ARCH_FEAT_SM100_ALL) || \
                               defined(__CUDA_ARCH_FEAT_SM101_ALL))
#define HAS_TCGEN05 1
#else
#define HAS_TCGEN05 0
#endif

// ---------------- GEMM tiling: cg1, BK=32, SW64, 6 stages, no cluster ----------------
#define BM   256
#define BN   256
#define BK   32
#define NC   (GK / BK)       // 128 chunks
#define NSTAGE 6

#define SMEM_TMEM_PTR 0
#define SMEM_FULL0    32     // full[s] = 32 + 8s   (6)
#define SMEM_DONE0    96     // done[s] = 96 + 8s   (6)
#define SMEM_ALLDONE  152    // single-phase completion barrier
#define SMEM_STAGE0   1024
#define STAGE_BYTES   32768  // A 16KB + B 16KB
#define STAGE_B_OFF   16384
#define SMEM_TRANS    (SMEM_STAGE0 + NSTAGE * STAGE_BYTES)      // 197632
#define TRANS_BYTES   (32 * 68 * 4)                             // 8704
#define SMEM_BYTES    (SMEM_TRANS + TRANS_BYTES)                // 206336

// idesc kind::f16 cg1: F32 accum, f16 inputs, N=128, M=128
#define MMA_IDESC  ((1u << 4) | (16u << 17) | (8u << 24))

// prep: ksp0 transpose only (zz 0,1) = 8192 tiles + pack 4096
#define NTBLK 8192
#define NPBLK 4096
#define NPREP (NTBLK + NPBLK)

// ---------------- device scratch ----------------
__device__ __half g_Af16[(size_t)BB * GK];        // [1024][4096] packed xh fp16
__device__ __half g_Wt  [(size_t)GN * GK];        // [8192][4096] fp16 K-major, gate-permuted
__device__ int    g_wdone;                        // CTAs done transposing ksp1
__device__ int    g_exit;                         // exit counter (resets the above)

// ---------------- generic helpers ----------------
__device__ __forceinline__ uint32_t smem_u32(const void* p) {
    uint32_t a;
    asm("{ .reg .u64 t; cvta.to.shared.u64 t, %1; cvt.u32.u64 %0, t; }" : "=r"(a) : "l"(p));
    return a;
}
__device__ __forceinline__ float sigmoidf_(float v) { return 1.f / (1.f + expf(-v)); }

// ================= preprocessing: ksp0 transpose + A pack =================
__global__ __launch_bounds__(256)
void prep_kernel(const float* __restrict__ x, const float* __restrict__ h,
                 const float* __restrict__ W) {
    const int bid = blockIdx.x;
    const int tid = threadIdx.x;

    if (bid < NTBLK) {
        __shared__ float tile[32][68];
        const int zz  = bid >> 12;                  // 0,1 -> ksp=0, nsp=zz
        const int rem = bid & 4095;
        const int dT  = rem >> 6;
        const int fT  = rem & 63;
        const int ksp = zz >> 1, nsp = zz & 1;      // ksp always 0 here
        const int dBase = dT * 32, fBase = fT * 64;
        const float* src = W + ((size_t)zz * 2048 + dBase) * 4096 + fBase;

        #pragma unroll
        for (int p = 0; p < 2; ++p) {
            const int idx = tid + 256 * p;
            const int r  = idx >> 4;
            const int c4 = idx & 15;
            const float4 v = *reinterpret_cast<const float4*>(src + (size_t)r * 4096 + c4 * 4);
            *reinterpret_cast<float4*>(&tile[r][c4 * 4]) = v;
        }
        __syncthreads();

        const int gate = fBase >> 10;
        const int uu0  = fBase & 1023;
        #pragma unroll
        for (int p = 0; p < 2; ++p) {
            const int idx = tid + 256 * p;
            const int i  = idx >> 3;
            const int r0 = (idx & 7) * 4;
            __half2 h0 = __floats2half2_rn(tile[r0 + 0][i], tile[r0 + 1][i]);
            __half2 h1 = __floats2half2_rn(tile[r0 + 2][i], tile[r0 + 3][i]);
            uint2 o;
            o.x = *reinterpret_cast<uint32_t*>(&h0);
            o.y = *reinterpret_cast<uint32_t*>(&h1);
            const int np = nsp * 4096 + (uu0 + i) * 4 + gate;
            *reinterpret_cast<uint2*>(&g_Wt[(size_t)np * GK + ksp * 2048 + dBase + r0]) = o;
        }
    } else {
        const int gi = (bid - NTBLK) * 256 + tid;
        const int b  = gi >> 10;
        const int k  = (gi & 1023) * 4;
        const int ksp = k >> 11;
        const int d   = k & 2047;
        const float* src = (d < 1024) ? (x + (size_t)b * UU + ksp * 1024 + d)
                                      : (h + (size_t)b * UU + ksp * 1024 + (d - 1024));
        const float4 v = *reinterpret_cast<const float4*>(src);
        __half2 p0 = __floats2half2_rn(v.x, v.y);
        __half2 p1 = __floats2half2_rn(v.z, v.w);
        uint2 o;
        o.x = *reinterpret_cast<uint32_t*>(&p0);
        o.y = *reinterpret_cast<uint32_t*>(&p1);
        *reinterpret_cast<uint2*>(&g_Af16[(size_t)b * GK + k]) = o;
    }
}

// ================= arch-specific helpers =================
#if HAS_TCGEN05
__device__ __forceinline__ uint32_t elect_one() {
    uint32_t pred;
    asm volatile("{\n\t.reg .pred p;\n\telect.sync _|p, 0xFFFFFFFF;\n\t"
                 "selp.b32 %0, 1, 0, p;\n\t}" : "=r"(pred));
    return pred;
}
// SW64 K-major smem descriptor: layout=4 (SW64), version=1, SBO=32, LBO=1
#define DESC_BASE ((uint64_t(4) << 61) | (uint64_t(1) << 46) | (uint64_t(32) << 32) | (uint64_t(1) << 16))
#define MK_DESC(addr) (DESC_BASE | ((uint64_t)((addr) >> 4) & 0x3FFF))

__device__ __forceinline__ void mma_f16_ss(uint32_t d, uint64_t ad, uint64_t bd,
                                           uint32_t idesc, uint32_t en) {
    asm volatile(
        "{\n\t.reg .pred p;\n\tsetp.ne.u32 p, %4, 0;\n\t"
        "tcgen05.mma.cta_group::1.kind::f16 [%0], %1, %2, %3, {%5,%5,%5,%5}, p;\n\t}"
        :: "r"(d), "l"(ad), "l"(bd), "r"(idesc), "r"(en), "r"(0u) : "memory");
}
#define MBAR_INIT(a, c)  asm volatile("mbarrier.init.shared.b64 [%0], %1;" :: "r"(a), "r"(c) : "memory")
#define MBAR_EXPECT_TX(a, n) asm volatile("mbarrier.arrive.expect_tx.shared.b64 _, [%0], %1;" :: "r"(a), "r"(n) : "memory")
#define TC_COMMIT(a)     asm volatile("tcgen05.commit.cta_group::1.mbarrier::arrive::one.shared::cluster.b64 [%0];" :: "r"(a) : "memory")
#define TC_ALLOC(sa, n)  asm volatile("tcgen05.alloc.cta_group::1.sync.aligned.shared::cta.b32 [%0], %1;" :: "r"(sa), "r"(n) : "memory")
#define TC_DEALLOC(t, n) asm volatile("tcgen05.dealloc.cta_group::1.sync.aligned.b32 %0, %1;" :: "r"(t), "r"(n))
#define TC_RELINQ()      asm volatile("tcgen05.relinquish_alloc_permit.cta_group::1.sync.aligned;")
#define TC_FENCE_AFTER() asm volatile("tcgen05.fence::after_thread_sync;" ::: "memory")
#define TC_WAIT_LD()     asm volatile("tcgen05.wait::ld.sync.aligned;" ::: "memory")
#define BAR_SYNC(id, n)  asm volatile("bar.sync %0, %1;" :: "r"(id), "r"(n) : "memory")

__device__ __forceinline__ void mbar_wait(uint32_t mbar, uint32_t parity) {
    asm volatile(
        "{\n\t.reg .pred P;\n\t"
        "W%=:\n\t"
        "mbarrier.try_wait.parity.acquire.cta.shared::cta.b64 P, [%0], %1, 0x989680;\n\t"
        "@P bra.uni D%=;\n\t"
        "bra.uni W%=;\n\t"
        "D%=:\n\t}"
        :: "r"(mbar), "r"(parity) : "memory");
}

__device__ __forceinline__ void tma2d(uint32_t dst, const void* tmap,
                                      int cx, int cy, uint32_t mbar) {
    asm volatile(
        "cp.async.bulk.tensor.2d.shared::cta.global.tile.mbarrier::complete_tx::bytes "
        "[%0], [%1, {%2, %3}], [%4];"
        :: "r"(dst), "l"(tmap), "r"(cx), "r"(cy), "r"(mbar) : "memory");
}

__device__ __forceinline__ void ldtm32(uint32_t* r, uint32_t addr) {
    asm volatile(
        "tcgen05.ld.sync.aligned.32x32b.x32.b32 "
        "{%0,%1,%2,%3,%4,%5,%6,%7,%8,%9,%10,%11,%12,%13,%14,%15,"
        "%16,%17,%18,%19,%20,%21,%22,%23,%24,%25,%26,%27,%28,%29,%30,%31}, [%32];"
        : "=r"(r[0]), "=r"(r[1]), "=r"(r[2]), "=r"(r[3]), "=r"(r[4]), "=r"(r[5]), "=r"(r[6]), "=r"(r[7]),
          "=r"(r[8]), "=r"(r[9]), "=r"(r[10]), "=r"(r[11]), "=r"(r[12]), "=r"(r[13]), "=r"(r[14]), "=r"(r[15]),
          "=r"(r[16]), "=r"(r[17]), "=r"(r[18]), "=r"(r[19]), "=r"(r[20]), "=r"(r[21]), "=r"(r[22]), "=r"(r[23]),
          "=r"(r[24]), "=r"(r[25]), "=r"(r[26]), "=r"(r[27]), "=r"(r[28]), "=r"(r[29]), "=r"(r[30]), "=r"(r[31])
        : "r"(addr));
}
#endif

// ================= GEMM + in-kernel ksp1 transpose + fused gates =================
// grid (4, 32): x = row tile (fastest), y = 256-col tile. 128 CTAs.
// Warps 0,1: producer/consumer (chunks 0..63 need only ksp0 = prep output).
// Warps 2-7: transpose W ksp1 (zz 2,3) -> Wt[:, 2048:4096], then raise g_wdone.
// Producer gates chunk 64 on g_wdone == 128.
__global__ __launch_bounds__(256, 1)
void lstm_gemm_tc(const __grid_constant__ CUtensorMap tmapA,
                  const __grid_constant__ CUtensorMap tmapB,
                  const float* __restrict__ W,
                  const float* __restrict__ c, float* __restrict__ out) {
#if HAS_TCGEN05
    extern __shared__ char smem_raw[];
    const uint32_t sbase = smem_u32(smem_raw);
    const int tid  = threadIdx.x;
    const int warp = tid >> 5;
    const int lane = tid & 31;

    const int rowBase = blockIdx.x * BM;
    const int colBase = blockIdx.y * BN;
    const int ctaId   = blockIdx.y * 4 + blockIdx.x;   // 0..127

    if (warp == 0) { TC_ALLOC(sbase + SMEM_TMEM_PTR, 512); }
    else           { TC_RELINQ(); }
    __syncthreads();
    uint32_t tmem_base;
    asm volatile("ld.shared.b32 %0, [%1];" : "=r"(tmem_base) : "r"(sbase + SMEM_TMEM_PTR));

    if (tid == 0) {
        #pragma unroll
        for (int s = 0; s < NSTAGE; ++s) {
            MBAR_INIT(sbase + SMEM_FULL0 + 8 * s, 1);
            MBAR_INIT(sbase + SMEM_DONE0 + 8 * s, 1);
        }
        MBAR_INIT(sbase + SMEM_ALLDONE, 1);
    }
    __syncthreads();

    // ================= TRANSPOSERS: warps 2-7 (192 threads, barrier id 1) =================
    if (warp >= 2) {
        const int tid2 = tid - 64;                  // 0..191
        float* tbuf = reinterpret_cast<float*>(smem_raw + SMEM_TRANS);   // [32][68]
        for (int j = 0; j < 64; ++j) {
            const int t   = ctaId * 64 + j;         // 0..8191
            const int zz  = 2 + (t >> 12);          // 2,3 -> ksp=1
            const int rem = t & 4095;
            const int dT  = rem >> 6;
            const int fT  = rem & 63;
            const int nsp = zz & 1;
            const int dBase = dT * 32, fBase = fT * 64;
            const float* src = W + ((size_t)zz * 2048 + dBase) * 4096 + fBase;

            #pragma unroll
            for (int p = 0; p < 3; ++p) {
                const int idx = tid2 + 192 * p;
                if (idx < 512) {
                    const int r  = idx >> 4;
                    const int c4 = idx & 15;
                    const float4 v = *reinterpret_cast<const float4*>(src + (size_t)r * 4096 + c4 * 4);
                    *reinterpret_cast<float4*>(&tbuf[r * 68 + c4 * 4]) = v;
                }
            }
            BAR_SYNC(1, 192);

            const int gate = fBase >> 10;
            const int uu0  = fBase & 1023;
            #pragma unroll
            for (int p = 0; p < 3; ++p) {
                const int idx = tid2 + 192 * p;
                if (idx < 512) {
                    const int i  = idx >> 3;
                    const int r0 = (idx & 7) * 4;
                    __half2 h0 = __floats2half2_rn(tbuf[(r0 + 0) * 68 + i], tbuf[(r0 + 1) * 68 + i]);
                    __half2 h1 = __floats2half2_rn(tbuf[(r0 + 2) * 68 + i], tbuf[(r0 + 3) * 68 + i]);
                    uint2 o;
                    o.x = *reinterpret_cast<uint32_t*>(&h0);
                    o.y = *reinterpret_cast<uint32_t*>(&h1);
                    const int np = nsp * 4096 + (uu0 + i) * 4 + gate;
                    *reinterpret_cast<uint2*>(&g_Wt[(size_t)np * GK + 2048 + dBase + r0]) = o;
                }
            }
            BAR_SYNC(1, 192);
        }
        if (tid == 64) {                            // warp 2 lane 0
            __threadfence();                        // Wt ksp1 visible gpu-wide
            atomicAdd(&g_wdone, 1);
        }
    }

    // ================= PRODUCER: warp 1, one thread =================
    if (warp == 1 && elect_one()) {
        for (int cc = 0; cc < NC; ++cc) {
            if (cc == 64) {                         // ksp1 must be fully transposed
                int v;
                do {
                    asm volatile("ld.acquire.gpu.global.b32 %0, [%1];"
                                 : "=r"(v) : "l"(&g_wdone) : "memory");
                    if (v < 128) __nanosleep(128);
                } while (v < 128);
            }
            const uint32_t s = (uint32_t)(cc % NSTAGE);
            if (cc >= NSTAGE) {
                mbar_wait(sbase + SMEM_DONE0 + 8 * s, (uint32_t)(((cc - NSTAGE) / NSTAGE) & 1));
            }
            const uint32_t fullb = sbase + SMEM_FULL0 + 8 * s;
            const uint32_t stA = sbase + SMEM_STAGE0 + s * STAGE_BYTES;
            const uint32_t stB = stA + STAGE_B_OFF;
            MBAR_EXPECT_TX(fullb, (uint32_t)32768);       // A 16KB + B 16KB
            tma2d(stA, &tmapA, cc * BK, rowBase, fullb);  // box 32k x 256 rows
            tma2d(stB, &tmapB, cc * BK, colBase, fullb);  // box 32k x 256 n
        }
    }

    // ================= CONSUMER: warp 0, one thread =================
    if (warp == 0 && elect_one()) {
        for (int it = 0; it < NC; ++it) {
            const uint32_t s = (uint32_t)(it % NSTAGE);
            mbar_wait(sbase + SMEM_FULL0 + 8 * s, (uint32_t)((it / NSTAGE) & 1));
            const uint32_t st = sbase + SMEM_STAGE0 + s * STAGE_BYTES;
            const uint64_t aD = MK_DESC(st);
            const uint64_t bD = MK_DESC(st + STAGE_B_OFF);
            // SW64: m/hh subtile = 128 rows x 64B = 512 units; ks = 32B = 2 units
            #pragma unroll
            for (int m = 0; m < 2; ++m)
                #pragma unroll
                for (int hh = 0; hh < 2; ++hh) {
                    const uint32_t dcol = tmem_base + m * 256 + hh * 128;
                    #pragma unroll
                    for (int ks = 0; ks < 2; ++ks)
                        mma_f16_ss(dcol, aD + m * 512 + ks * 2, bD + hh * 512 + ks * 2,
                                   MMA_IDESC, (uint32_t)(it > 0 || ks > 0));
                }
            TC_COMMIT(sbase + SMEM_DONE0 + 8 * s);        // local stage recycle
        }
        TC_COMMIT(sbase + SMEM_ALLDONE);                  // all local MMAs done
    }

    __syncthreads();
    mbar_wait(sbase + SMEM_ALLDONE, 0u);
    TC_FENCE_AFTER();

    // ---- fused gate epilogue ----
    {
        const int m   = warp >> 2;
        const int sub = warp & 3;
        const int b   = rowBase + m * 128 + sub * 32 + lane;
        const int nsp    = colBase >> 12;
        const int uuBase = (colBase & 4095) >> 2;
        const float* cRow = c + (size_t)b * UU;
        float* outH = out + (size_t)b * UU;
        float* outC = out + (size_t)BB * UU + (size_t)b * UU;

        uint32_t regs[32];
        #pragma unroll
        for (int cb = 0; cb < 8; ++cb) {
            ldtm32(regs, tmem_base + m * 256 + cb * 32);
            TC_WAIT_LD();
            const int u0 = nsp * 1024 + uuBase + cb * 8;
            float cArr[8], hArr[8], nArr[8];
            *reinterpret_cast<float4*>(&cArr[0]) = *reinterpret_cast<const float4*>(cRow + u0);
            *reinterpret_cast<float4*>(&cArr[4]) = *reinterpret_cast<const float4*>(cRow + u0 + 4);
            #pragma unroll
            for (int j = 0; j < 8; ++j) {
                const float ig = sigmoidf_(__uint_as_float(regs[4 * j + 0]));
                const float fg = sigmoidf_(__uint_as_float(regs[4 * j + 1]));
                const float gg = tanhf(__uint_as_float(regs[4 * j + 2]));
                const float og = sigmoidf_(__uint_as_float(regs[4 * j + 3]));
                const float nc = fg * cArr[j] + ig * gg;
                nArr[j] = nc;
                hArr[j] = og * tanhf(nc);
            }
            *reinterpret_cast<float4*>(outH + u0)     = *reinterpret_cast<float4*>(&hArr[0]);
            *reinterpret_cast<float4*>(outH + u0 + 4) = *reinterpret_cast<float4*>(&hArr[4]);
            *reinterpret_cast<float4*>(outC + u0)     = *reinterpret_cast<float4*>(&nArr[0]);
            *reinterpret_cast<float4*>(outC + u0 + 4) = *reinterpret_cast<float4*>(&nArr[4]);
        }
    }

    __syncthreads();
    if (warp == 0) { TC_DEALLOC(tmem_base, 512); }
    __syncthreads();
    // reset global counters for the next graph replay (last CTA to exit does it)
    if (tid == 0) {
        const int old = atomicAdd(&g_exit, 1);
        if (old == 127) { g_exit = 0; g_wdone = 0; }
    }

#else
    // ===== baseline-arch fallback (compile-correct; not selected on sm_103a) =====
    const int tid = threadIdx.x;
    const int rowBase = blockIdx.x * BM;
    const int colBase = blockIdx.y * BN;
    const int nsp    = colBase >> 12;
    const int uuBase = (colBase & 4095) >> 2;
    const int b = rowBase + tid;
    const __half* arow = g_Af16 + (size_t)b * GK;
    for (int j = 0; j < 64; ++j) {
        const __half* brow = g_Wt + (size_t)(colBase + j * 4) * GK;
        float acc[4] = {0.f, 0.f, 0.f, 0.f};
        for (int k = 0; k < GK; ++k) {
            const float a = __half2float(arow[k]);
            acc[0] += a * __half2float(brow[k]);
            acc[1] += a * __half2float(brow[(size_t)GK + k]);
            acc[2] += a * __half2float(brow[(size_t)2 * GK + k]);
            acc[3] += a * __half2float(brow[(size_t)3 * GK + k]);
        }
        const int u = nsp * 1024 + uuBase + j;
        const float ig = sigmoidf_(acc[0]);
        const float fg = sigmoidf_(acc[1]);
        const float gg = tanhf(acc[2]);
        const float og = sigmoidf_(acc[3]);
        const float cin = c[(size_t)b * UU + u];
        const float nc = fg * cin + ig * gg;
        out[(size_t)b * UU + u] = og * tanhf(nc);
        out[(size_t)BB * UU + (size_t)b * UU + u] = nc;
    }
    (void)W;
#endif
}

// ================= launch =================
typedef CUresult (*PFN_encodeTiled_t)(
    CUtensorMap*, CUtensorMapDataType, cuuint32_t, void*,
    const cuuint64_t*, const cuuint64_t*, const cuuint32_t*, const cuuint32_t*,
    CUtensorMapInterleave, CUtensorMapSwizzle, CUtensorMapL2promotion,
    CUtensorMapFloatOOBfill);

extern "C" void kernel_launch(void* const* d_in, const int* in_sizes, int n_in,
                              void* d_out, int out_size) {
    const float* x = (const float*)d_in[0];
    const float* h = (const float*)d_in[1];
    const float* c = (const float*)d_in[2];
    const float* W = (const float*)d_in[3];
    float* out = (float*)d_out;

    cudaFuncSetAttribute(lstm_gemm_tc, cudaFuncAttributeMaxDynamicSharedMemorySize, SMEM_BYTES);

    void* fn = nullptr;
    cudaDriverEntryPointQueryResult qres;
    cudaGetDriverEntryPoint("cuTensorMapEncodeTiled", &fn, cudaEnableDefault, &qres);
    PFN_encodeTiled_t enc = (PFN_encodeTiled_t)fn;

    // A tensormap: g_Af16 [1024 rows][4096 k] fp16, box [32 k x 256 rows], SW64
    CUtensorMap tmapA;
    {
        void* aPtr = nullptr;
        cudaGetSymbolAddress(&aPtr, g_Af16);
        cuuint64_t dims[2]    = {GK, BB};
        cuuint64_t strides[1] = {(cuuint64_t)GK * 2};
        cuuint32_t box[2]     = {32, 256};          // 32 f16 = 64B = SW64 span
        cuuint32_t estr[2]    = {1, 1};
        enc(&tmapA, CU_TENSOR_MAP_DATA_TYPE_FLOAT16, 2, aPtr,
            dims, strides, box, estr,
            CU_TENSOR_MAP_INTERLEAVE_NONE, CU_TENSOR_MAP_SWIZZLE_64B,
            CU_TENSOR_MAP_L2_PROMOTION_L2_128B, CU_TENSOR_MAP_FLOAT_OOB_FILL_NONE);
    }
    // B tensormap: g_Wt [8192 n][4096 k] fp16, box [32 k x 256 n], SW64
    CUtensorMap tmapB;
    {
        void* wtPtr = nullptr;
        cudaGetSymbolAddress(&wtPtr, g_Wt);
        cuuint64_t dims[2]    = {GK, GN};
        cuuint64_t strides[1] = {(cuuint64_t)GK * 2};
        cuuint32_t box[2]     = {32, 256};
        cuuint32_t estr[2]    = {1, 1};
        enc(&tmapB, CU_TENSOR_MAP_DATA_TYPE_FLOAT16, 2, wtPtr,
            dims, strides, box, estr,
            CU_TENSOR_MAP_INTERLEAVE_NONE, CU_TENSOR_MAP_SWIZZLE_64B,
            CU_TENSOR_MAP_L2_PROMOTION_L2_128B, CU_TENSOR_MAP_FLOAT_OOB_FILL_NONE);
    }

    prep_kernel<<<NPREP, 256>>>(x, h, W);
    lstm_gemm_tc<<<dim3(4, 32), 256, SMEM_BYTES>>>(tmapA, tmapB, W, c, out);
}

// round 16
// speedup vs baseline: 1.4456x; 1.4456x over previous
#include <cuda_runtime.h>
#include <cuda_fp16.h>
#include <cuda.h>
#include <cstdint>
#include <math.h>

// ---------------- problem constants ----------------
#define BB   1024
#define UU   2048
#define GK   4096            // GEMM K = 2U
#define GN   8192            // GEMM N = 4U

// ---------------- arch gate ----------------
#if defined(__CUDA_ARCH__) && (defined(__CUDA_ARCH_FEAT_SM103_ALL) || \
                               defined(__CUDA_ARCH_FEAT_SM100_ALL) || \
                               defined(__CUDA_ARCH_FEAT_SM101_ALL))
#define HAS_TCGEN05 1
#else
#define HAS_TCGEN05 0
#endif

// ---------------- GEMM tiling: cg1, BK=32, SW64, 7 stages, no cluster ----------------
#define BM   256
#define BN   256
#define BK   32
#define NC   (GK / BK)       // 128 chunks
#define NSTAGE 7

#define SMEM_TMEM_PTR 0
#define SMEM_FULL0    32     // full[s] = 32 + 8s   (7)
#define SMEM_DONE0    96     // done[s] = 96 + 8s   (7)
#define SMEM_ALLDONE  160    // single-phase completion barrier
#define SMEM_STAGE0   1024
#define STAGE_BYTES   32768  // A 16KB + B 16KB
#define STAGE_B_OFF   16384
#define SMEM_BYTES    (1024 + NSTAGE * STAGE_BYTES)   // 230400 (<= 232448 cap)

// idesc kind::f16 cg1: F32 accum, f16 inputs, N=128, M=128
#define MMA_IDESC  ((1u << 4) | (16u << 17) | (8u << 24))

// prep: transpose = 4 zz x 64 dT x 64 fT = 16384; pack = 4096
#define NTBLK 16384
#define NPBLK 4096
#define NPREP (NTBLK + NPBLK)

// ---------------- device scratch ----------------
__device__ __half g_Af16[(size_t)BB * GK];        // [1024][4096] packed xh fp16
__device__ __half g_Wt  [(size_t)GN * GK];        // [8192][4096] fp16 K-major, gate-permuted

// ---------------- generic helpers ----------------
__device__ __forceinline__ uint32_t smem_u32(const void* p) {
    uint32_t a;
    asm("{ .reg .u64 t; cvta.to.shared.u64 t, %1; cvt.u32.u64 %0, t; }" : "=r"(a) : "l"(p));
    return a;
}
__device__ __forceinline__ float sigmoidf_(float v) { return 1.f / (1.f + expf(-v)); }

// ================= fused preprocessing: conflict-free smem (stride 65) =================
__global__ __launch_bounds__(256)
void prep_kernel(const float* __restrict__ x, const float* __restrict__ h,
                 const float* __restrict__ W) {
    const int bid = blockIdx.x;
    const int tid = threadIdx.x;

    if (bid < NTBLK) {
        __shared__ float tile[32 * 65];             // stride 65: both phases bank-conflict-free
        const int zz  = bid >> 12;                  // ksp*2 + nsp
        const int rem = bid & 4095;
        const int dT  = rem >> 6;
        const int fT  = rem & 63;
        const int ksp = zz >> 1, nsp = zz & 1;
        const int dBase = dT * 32, fBase = fT * 64;
        const float* src = W + ((size_t)zz * 2048 + dBase) * 4096 + fBase;

        // load 32 rows x 64 floats; scalar STS (stride-65 rows are not 16B aligned)
        #pragma unroll
        for (int p = 0; p < 2; ++p) {
            const int idx = tid + 256 * p;
            const int r  = idx >> 4;
            const int c4 = idx & 15;
            const float4 v = *reinterpret_cast<const float4*>(src + (size_t)r * 4096 + c4 * 4);
            float* dst = &tile[r * 65 + c4 * 4];
            dst[0] = v.x; dst[1] = v.y; dst[2] = v.z; dst[3] = v.w;
        }
        __syncthreads();

        const int gate = fBase >> 10;
        const int uu0  = fBase & 1023;
        #pragma unroll
        for (int p = 0; p < 2; ++p) {
            const int idx = tid + 256 * p;
            const int i  = idx >> 3;                // f row (8 lanes share i)
            const int r0 = (idx & 7) * 4;           // k chunk: banks (4j+i)%32 all distinct
            const float a0 = tile[(r0 + 0) * 65 + i];
            const float a1 = tile[(r0 + 1) * 65 + i];
            const float a2 = tile[(r0 + 2) * 65 + i];
            const float a3 = tile[(r0 + 3) * 65 + i];
            __half2 h0 = __floats2half2_rn(a0, a1);
            __half2 h1 = __floats2half2_rn(a2, a3);
            uint2 o;
            o.x = *reinterpret_cast<uint32_t*>(&h0);
            o.y = *reinterpret_cast<uint32_t*>(&h1);
            const int np = nsp * 4096 + (uu0 + i) * 4 + gate;
            *reinterpret_cast<uint2*>(&g_Wt[(size_t)np * GK + ksp * 2048 + dBase + r0]) = o;
        }
    } else {
        const int gi = (bid - NTBLK) * 256 + tid;
        const int b  = gi >> 10;
        const int k  = (gi & 1023) * 4;
        const int ksp = k >> 11;
        const int d   = k & 2047;
        const float* src = (d < 1024) ? (x + (size_t)b * UU + ksp * 1024 + d)
                                      : (h + (size_t)b * UU + ksp * 1024 + (d - 1024));
        const float4 v = *reinterpret_cast<const float4*>(src);
        __half2 p0 = __floats2half2_rn(v.x, v.y);
        __half2 p1 = __floats2half2_rn(v.z, v.w);
        uint2 o;
        o.x = *reinterpret_cast<uint32_t*>(&p0);
        o.y = *reinterpret_cast<uint32_t*>(&p1);
        *reinterpret_cast<uint2*>(&g_Af16[(size_t)b * GK + k]) = o;
    }
}

// ================= arch-specific helpers =================
#if HAS_TCGEN05
__device__ __forceinline__ uint32_t elect_one() {
    uint32_t pred;
    asm volatile("{\n\t.reg .pred p;\n\telect.sync _|p, 0xFFFFFFFF;\n\t"
                 "selp.b32 %0, 1, 0, p;\n\t}" : "=r"(pred));
    return pred;
}
// SW64 K-major smem descriptor: layout=4 (SW64), version=1, SBO=32, LBO=1
#define DESC_BASE ((uint64_t(4) << 61) | (uint64_t(1) << 46) | (uint64_t(32) << 32) | (uint64_t(1) << 16))
#define MK_DESC(addr) (DESC_BASE | ((uint64_t)((addr) >> 4) & 0x3FFF))

__device__ __forceinline__ void mma_f16_ss(uint32_t d, uint64_t ad, uint64_t bd,
                                           uint32_t idesc, uint32_t en) {
    asm volatile(
        "{\n\t.reg .pred p;\n\tsetp.ne.u32 p, %4, 0;\n\t"
        "tcgen05.mma.cta_group::1.kind::f16 [%0], %1, %2, %3, {%5,%5,%5,%5}, p;\n\t}"
        :: "r"(d), "l"(ad), "l"(bd), "r"(idesc), "r"(en), "r"(0u) : "memory");
}
#define MBAR_INIT(a, c)  asm volatile("mbarrier.init.shared.b64 [%0], %1;" :: "r"(a), "r"(c) : "memory")
#define MBAR_EXPECT_TX(a, n) asm volatile("mbarrier.arrive.expect_tx.shared.b64 _, [%0], %1;" :: "r"(a), "r"(n) : "memory")
#define TC_COMMIT(a)     asm volatile("tcgen05.commit.cta_group::1.mbarrier::arrive::one.shared::cluster.b64 [%0];" :: "r"(a) : "memory")
#define TC_ALLOC(sa, n)  asm volatile("tcgen05.alloc.cta_group::1.sync.aligned.shared::cta.b32 [%0], %1;" :: "r"(sa), "r"(n) : "memory")
#define TC_DEALLOC(t, n) asm volatile("tcgen05.dealloc.cta_group::1.sync.aligned.b32 %0, %1;" :: "r"(t), "r"(n))
#define TC_RELINQ()      asm volatile("tcgen05.relinquish_alloc_permit.cta_group::1.sync.aligned;")
#define TC_FENCE_AFTER() asm volatile("tcgen05.fence::after_thread_sync;" ::: "memory")
#define TC_WAIT_LD()     asm volatile("tcgen05.wait::ld.sync.aligned;" ::: "memory")

__device__ __forceinline__ void mbar_wait(uint32_t mbar, uint32_t parity) {
    asm volatile(
        "{\n\t.reg .pred P;\n\t"
        "W%=:\n\t"
        "mbarrier.try_wait.parity.acquire.cta.shared::cta.b64 P, [%0], %1, 0x989680;\n\t"
        "@P bra.uni D%=;\n\t"
        "bra.uni W%=;\n\t"
        "D%=:\n\t}"
        :: "r"(mbar), "r"(parity) : "memory");
}

__device__ __forceinline__ void tma2d(uint32_t dst, const void* tmap,
                                      int cx, int cy, uint32_t mbar) {
    asm volatile(
        "cp.async.bulk.tensor.2d.shared::cta.global.tile.mbarrier::complete_tx::bytes "
        "[%0], [%1, {%2, %3}], [%4];"
        :: "r"(dst), "l"(tmap), "r"(cx), "r"(cy), "r"(mbar) : "memory");
}

__device__ __forceinline__ void ldtm32(uint32_t* r, uint32_t addr) {
    asm volatile(
        "tcgen05.ld.sync.aligned.32x32b.x32.b32 "
        "{%0,%1,%2,%3,%4,%5,%6,%7,%8,%9,%10,%11,%12,%13,%14,%15,"
        "%16,%17,%18,%19,%20,%21,%22,%23,%24,%25,%26,%27,%28,%29,%30,%31}, [%32];"
        : "=r"(r[0]), "=r"(r[1]), "=r"(r[2]), "=r"(r[3]), "=r"(r[4]), "=r"(r[5]), "=r"(r[6]), "=r"(r[7]),
          "=r"(r[8]), "=r"(r[9]), "=r"(r[10]), "=r"(r[11]), "=r"(r[12]), "=r"(r[13]), "=r"(r[14]), "=r"(r[15]),
          "=r"(r[16]), "=r"(r[17]), "=r"(r[18]), "=r"(r[19]), "=r"(r[20]), "=r"(r[21]), "=r"(r[22]), "=r"(r[23]),
          "=r"(r[24]), "=r"(r[25]), "=r"(r[26]), "=r"(r[27]), "=r"(r[28]), "=r"(r[29]), "=r"(r[30]), "=r"(r[31])
        : "r"(addr));
}
#endif

// ================= GEMM + fused gates: cg1, local-only pipeline (R14 + 7 stages) =================
// grid (4, 32): x = row tile (fastest -> 4 CTAs sharing a B panel co-resident, B via L2).
__global__ __launch_bounds__(256, 1)
void lstm_gemm_tc(const __grid_constant__ CUtensorMap tmapA,
                  const __grid_constant__ CUtensorMap tmapB,
                  const float* __restrict__ c, float* __restrict__ out) {
#if HAS_TCGEN05
    extern __shared__ char smem_raw[];
    const uint32_t sbase = smem_u32(smem_raw);
    const int tid  = threadIdx.x;
    const int warp = tid >> 5;
    const int lane = tid & 31;

    const int rowBase = blockIdx.x * BM;
    const int colBase = blockIdx.y * BN;

    if (warp == 0) { TC_ALLOC(sbase + SMEM_TMEM_PTR, 512); }
    else           { TC_RELINQ(); }
    __syncthreads();
    uint32_t tmem_base;
    asm volatile("ld.shared.b32 %0, [%1];" : "=r"(tmem_base) : "r"(sbase + SMEM_TMEM_PTR));

    if (tid == 0) {
        #pragma unroll
        for (int s = 0; s < NSTAGE; ++s) {
            MBAR_INIT(sbase + SMEM_FULL0 + 8 * s, 1);   // expect_tx per round
            MBAR_INIT(sbase + SMEM_DONE0 + 8 * s, 1);   // 1 LOCAL commit per round
        }
        MBAR_INIT(sbase + SMEM_ALLDONE, 1);             // single-phase, unambiguous
    }
    __syncthreads();

    // ================= PRODUCER: warp 1, one thread =================
    if (warp == 1 && elect_one()) {
        for (int cc = 0; cc < NC; ++cc) {
            const uint32_t s = (uint32_t)(cc % NSTAGE);
            if (cc >= NSTAGE) {
                mbar_wait(sbase + SMEM_DONE0 + 8 * s, (uint32_t)(((cc - NSTAGE) / NSTAGE) & 1));
            }
            const uint32_t fullb = sbase + SMEM_FULL0 + 8 * s;
            const uint32_t stA = sbase + SMEM_STAGE0 + s * STAGE_BYTES;
            const uint32_t stB = stA + STAGE_B_OFF;
            MBAR_EXPECT_TX(fullb, (uint32_t)32768);       // A 16KB + B 16KB
            tma2d(stA, &tmapA, cc * BK, rowBase, fullb);  // box 32k x 256 rows
            tma2d(stB, &tmapB, cc * BK, colBase, fullb);  // box 32k x 256 n
        }
    }

    // ================= CONSUMER: warp 0, one thread =================
    if (warp == 0 && elect_one()) {
        for (int it = 0; it < NC; ++it) {
            const uint32_t s = (uint32_t)(it % NSTAGE);
            mbar_wait(sbase + SMEM_FULL0 + 8 * s, (uint32_t)((it / NSTAGE) & 1));
            const uint32_t st = sbase + SMEM_STAGE0 + s * STAGE_BYTES;
            const uint64_t aD = MK_DESC(st);
            const uint64_t bD = MK_DESC(st + STAGE_B_OFF);
            // SW64: m/hh subtile = 128 rows x 64B = 512 units; ks = 32B = 2 units
            #pragma unroll
            for (int m = 0; m < 2; ++m)
                #pragma unroll
                for (int hh = 0; hh < 2; ++hh) {
                    const uint32_t dcol = tmem_base + m * 256 + hh * 128;
                    #pragma unroll
                    for (int ks = 0; ks < 2; ++ks)
                        mma_f16_ss(dcol, aD + m * 512 + ks * 2, bD + hh * 512 + ks * 2,
                                   MMA_IDESC, (uint32_t)(it > 0 || ks > 0));
                }
            TC_COMMIT(sbase + SMEM_DONE0 + 8 * s);        // local stage recycle
        }
        TC_COMMIT(sbase + SMEM_ALLDONE);                  // all local MMAs done
    }

    __syncthreads();
    mbar_wait(sbase + SMEM_ALLDONE, 0u);
    TC_FENCE_AFTER();

    // ---- fused gate epilogue ----
    {
        const int m   = warp >> 2;
        const int sub = warp & 3;
        const int b   = rowBase + m * 128 + sub * 32 + lane;
        const int nsp    = colBase >> 12;
        const int uuBase = (colBase & 4095) >> 2;
        const float* cRow = c + (size_t)b * UU;
        float* outH = out + (size_t)b * UU;
        float* outC = out + (size_t)BB * UU + (size_t)b * UU;

        uint32_t regs[32];
        #pragma unroll
        for (int cb = 0; cb < 8; ++cb) {
            ldtm32(regs, tmem_base + m * 256 + cb * 32);
            TC_WAIT_LD();
            const int u0 = nsp * 1024 + uuBase + cb * 8;
            float cArr[8], hArr[8], nArr[8];
            *reinterpret_cast<float4*>(&cArr[0]) = *reinterpret_cast<const float4*>(cRow + u0);
            *reinterpret_cast<float4*>(&cArr[4]) = *reinterpret_cast<const float4*>(cRow + u0 + 4);
            #pragma unroll
            for (int j = 0; j < 8; ++j) {
                const float ig = sigmoidf_(__uint_as_float(regs[4 * j + 0]));
                const float fg = sigmoidf_(__uint_as_float(regs[4 * j + 1]));
                const float gg = tanhf(__uint_as_float(regs[4 * j + 2]));
                const float og = sigmoidf_(__uint_as_float(regs[4 * j + 3]));
                const float nc = fg * cArr[j] + ig * gg;
                nArr[j] = nc;
                hArr[j] = og * tanhf(nc);
            }
            *reinterpret_cast<float4*>(outH + u0)     = *reinterpret_cast<float4*>(&hArr[0]);
            *reinterpret_cast<float4*>(outH + u0 + 4) = *reinterpret_cast<float4*>(&hArr[4]);
            *reinterpret_cast<float4*>(outC + u0)     = *reinterpret_cast<float4*>(&nArr[0]);
            *reinterpret_cast<float4*>(outC + u0 + 4) = *reinterpret_cast<float4*>(&nArr[4]);
        }
    }

    __syncthreads();
    if (warp == 0) { TC_DEALLOC(tmem_base, 512); }

#else
    // ===== baseline-arch fallback (compile-correct; not selected on sm_103a) =====
    const int tid = threadIdx.x;
    const int rowBase = blockIdx.x * BM;
    const int colBase = blockIdx.y * BN;
    const int nsp    = colBase >> 12;
    const int uuBase = (colBase & 4095) >> 2;
    const int b = rowBase + tid;
    const __half* arow = g_Af16 + (size_t)b * GK;
    for (int j = 0; j < 64; ++j) {
        const __half* brow = g_Wt + (size_t)(colBase + j * 4) * GK;
        float acc[4] = {0.f, 0.f, 0.f, 0.f};
        for (int k = 0; k < GK; ++k) {
            const float a = __half2float(arow[k]);
            acc[0] += a * __half2float(brow[k]);
            acc[1] += a * __half2float(brow[(size_t)GK + k]);
            acc[2] += a * __half2float(brow[(size_t)2 * GK + k]);
            acc[3] += a * __half2float(brow[(size_t)3 * GK + k]);
        }
        const int u = nsp * 1024 + uuBase + j;
        const float ig = sigmoidf_(acc[0]);
        const float fg = sigmoidf_(acc[1]);
        const float gg = tanhf(acc[2]);
        const float og = sigmoidf_(acc[3]);
        const float cin = c[(size_t)b * UU + u];
        const float nc = fg * cin + ig * gg;
        out[(size_t)b * UU + u] = og * tanhf(nc);
        out[(size_t)BB * UU + (size_t)b * UU + u] = nc;
    }
#endif
}

// ================= launch =================
typedef CUresult (*PFN_encodeTiled_t)(
    CUtensorMap*, CUtensorMapDataType, cuuint32_t, void*,
    const cuuint64_t*, const cuuint64_t*, const cuuint32_t*, const cuuint32_t*,
    CUtensorMapInterleave, CUtensorMapSwizzle, CUtensorMapL2promotion,
    CUtensorMapFloatOOBfill);

extern "C" void kernel_launch(void* const* d_in, const int* in_sizes, int n_in,
                              void* d_out, int out_size) {
    const float* x = (const float*)d_in[0];
    const float* h = (const float*)d_in[1];
    const float* c = (const float*)d_in[2];
    const float* W = (const float*)d_in[3];
    float* out = (float*)d_out;

    cudaFuncSetAttribute(lstm_gemm_tc, cudaFuncAttributeMaxDynamicSharedMemorySize, SMEM_BYTES);

    void* fn = nullptr;
    cudaDriverEntryPointQueryResult qres;
    cudaGetDriverEntryPoint("cuTensorMapEncodeTiled", &fn, cudaEnableDefault, &qres);
    PFN_encodeTiled_t enc = (PFN_encodeTiled_t)fn;

    // A tensormap: g_Af16 [1024 rows][4096 k] fp16, box [32 k x 256 rows], SW64
    CUtensorMap tmapA;
    {
        void* aPtr = nullptr;
        cudaGetSymbolAddress(&aPtr, g_Af16);
        cuuint64_t dims[2]    = {GK, BB};
        cuuint64_t strides[1] = {(cuuint64_t)GK * 2};
        cuuint32_t box[2]     = {32, 256};          // 32 f16 = 64B = SW64 span
        cuuint32_t estr[2]    = {1, 1};
        enc(&tmapA, CU_TENSOR_MAP_DATA_TYPE_FLOAT16, 2, aPtr,
            dims, strides, box, estr,
            CU_TENSOR_MAP_INTERLEAVE_NONE, CU_TENSOR_MAP_SWIZZLE_64B,
            CU_TENSOR_MAP_L2_PROMOTION_L2_128B, CU_TENSOR_MAP_FLOAT_OOB_FILL_NONE);
    }
    // B tensormap: g_Wt [8192 n][4096 k] fp16, box [32 k x 256 n], SW64
    CUtensorMap tmapB;
    {
        void* wtPtr = nullptr;
        cudaGetSymbolAddress(&wtPtr, g_Wt);
        cuuint64_t dims[2]    = {GK, GN};
        cuuint64_t strides[1] = {(cuuint64_t)GK * 2};
        cuuint32_t box[2]     = {32, 256};
        cuuint32_t estr[2]    = {1, 1};
        enc(&tmapB, CU_TENSOR_MAP_DATA_TYPE_FLOAT16, 2, wtPtr,
            dims, strides, box, estr,
            CU_TENSOR_MAP_INTERLEAVE_NONE, CU_TENSOR_MAP_SWIZZLE_64B,
            CU_TENSOR_MAP_L2_PROMOTION_L2_128B, CU_TENSOR_MAP_FLOAT_OOB_FILL_NONE);
    }

    prep_kernel<<<NPREP, 256>>>(x, h, W);
    lstm_gemm_tc<<<dim3(4, 32), 256, SMEM_BYTES>>>(tmapA, tmapB, c, out);
}